// round 2
// baseline (speedup 1.0000x reference)
#include <cuda_runtime.h>

// MS-G3D fused forward, fp32 baseline (round 2: fix host-side __device__ symbol
// addresses passed to k_stats — g_p1/g_p2 must go through cudaGetSymbolAddress).
// Shapes: N=8, C=96, T=128, V=25, WIN=3, VL=75, NS=6.
#define NB    8
#define CC    96
#define TT    128
#define VV    25
#define WINW  3
#define VLW   75
#define NSC   6
#define NTB   (NB*TT)          // 1024 (n,t) tiles
#define DIN   (CC*NSC*2)       // 1152
#define EPS_F 1e-5f

// ---------------- device scratch (static, allocation-free) ----------------
__device__ float g_Aeff[NSC*VLW*VLW];        // 33750
__device__ float g_Beff[NSC*VLW*VLW];        // 33750
__device__ float g_z1[NTB*CC*VLW];           // [n][t][o][vl]  29.5 MB
__device__ float g_outp[NTB*CC*VV];          // [n][t][o][v]    9.8 MB
__device__ float g_p1[NTB*CC*2];             // per-block channel partial (sum, sumsq)
__device__ float g_p2[NTB*CC*2];
__device__ float g_s1[CC*2];                 // (a1, c1) per channel
__device__ float g_s2[CC*2];                 // (a2, c2)

// ---------------- kernel 0: effective adjacency ----------------
__global__ void k_eff(const float* __restrict__ As, const float* __restrict__ Bs,
                      const float* __restrict__ Ar) {
    int i = blockIdx.x * blockDim.x + threadIdx.x;
    if (i < NSC*VLW*VLW) {
        float r = Ar[i];
        g_Aeff[i] = As[i] + r;
        g_Beff[i] = Bs[i] + r;
    }
}

// ---------------- kernel 1: fused unfold + 12x (W_bs @ Xu @ M_bs^T) + bias + relu ----------------
// grid: 1024 blocks (n*T+t), block: 256 threads (240 compute).
// smem layout (floats): Xu[96*76] | Wsh[96*97] | Msh[75*76] | Ysh[96*81]
#define XU_P 76
#define W_P  97
#define M_P  76
#define Y_P  81
#define SM1_FLOATS (CC*XU_P + CC*W_P + VLW*M_P + CC*Y_P)   // 30084 -> 120336 B

__global__ void k_aggmlp(const float* __restrict__ x,
                         const float* __restrict__ Wmlp,
                         const float* __restrict__ bmlp) {
    extern __shared__ float sm[];
    float* Xu  = sm;
    float* Wsh = Xu  + CC*XU_P;
    float* Msh = Wsh + CC*W_P;
    float* Ysh = Msh + VLW*M_P;

    const int blk = blockIdx.x;
    const int n = blk / TT;
    const int t = blk % TT;
    const int tid = threadIdx.x;

    // load Xu[c][u], u = w*25+v, temporal zero pad
    for (int e = tid; e < CC*VLW; e += blockDim.x) {
        int c = e / VLW, u = e % VLW;
        int w = u / VV, v = u % VV;
        int tt = t + w - 1;
        float val = 0.f;
        if (tt >= 0 && tt < TT)
            val = x[((n*CC + c)*TT + tt)*VV + v];
        Xu[c*XU_P + u] = val;
    }

    const int og = tid & 15;           // 0..15 -> o strip of 6
    const int ug = tid >> 4;           // 0..15 (active ug<15) -> u/v' strip of 5
    const int o0 = og * 6;
    const int u0 = ug * 5;
    const bool act = (tid < 240);

    float h2a[6][5];
#pragma unroll
    for (int i = 0; i < 6; i++)
#pragma unroll
        for (int j = 0; j < 5; j++) h2a[i][j] = 0.f;

    for (int bs = 0; bs < 12; bs++) {
        const int branch = bs / NSC;
        const int s = bs % NSC;
        const int woff = branch * (NSC*CC) + s * CC;
        const float* Mg = (branch == 0 ? g_Aeff : g_Beff) + s*VLW*VLW;

        // load W slice (96x96) and M slice (75x75)
        for (int e = tid; e < CC*CC; e += blockDim.x) {
            int o = e / CC, c = e % CC;
            Wsh[o*W_P + c] = Wmlp[o*DIN + woff + c];
        }
        for (int e = tid; e < VLW*VLW; e += blockDim.x) {
            int vp = e / VLW, u = e % VLW;
            Msh[vp*M_P + u] = Mg[e];
        }
        __syncthreads();

        if (act) {
            // stage A: Y = W @ Xu   (96x96 * 96x75)
            float acc[6][5];
#pragma unroll
            for (int i = 0; i < 6; i++)
#pragma unroll
                for (int j = 0; j < 5; j++) acc[i][j] = 0.f;

            for (int c = 0; c < CC; c++) {
                float xv0 = Xu[c*XU_P + u0 + 0];
                float xv1 = Xu[c*XU_P + u0 + 1];
                float xv2 = Xu[c*XU_P + u0 + 2];
                float xv3 = Xu[c*XU_P + u0 + 3];
                float xv4 = Xu[c*XU_P + u0 + 4];
#pragma unroll
                for (int i = 0; i < 6; i++) {
                    float w = Wsh[(o0 + i)*W_P + c];
                    acc[i][0] = fmaf(w, xv0, acc[i][0]);
                    acc[i][1] = fmaf(w, xv1, acc[i][1]);
                    acc[i][2] = fmaf(w, xv2, acc[i][2]);
                    acc[i][3] = fmaf(w, xv3, acc[i][3]);
                    acc[i][4] = fmaf(w, xv4, acc[i][4]);
                }
            }
#pragma unroll
            for (int i = 0; i < 6; i++)
#pragma unroll
                for (int j = 0; j < 5; j++)
                    Ysh[(o0 + i)*Y_P + u0 + j] = acc[i][j];
        }
        __syncthreads();

        if (act) {
            // stage B: h2 += Y @ M^T  (h2[o][v'] += sum_u Y[o][u] * M[v'][u])
            for (int u = 0; u < VLW; u++) {
                float yv0 = Ysh[(o0 + 0)*Y_P + u];
                float yv1 = Ysh[(o0 + 1)*Y_P + u];
                float yv2 = Ysh[(o0 + 2)*Y_P + u];
                float yv3 = Ysh[(o0 + 3)*Y_P + u];
                float yv4 = Ysh[(o0 + 4)*Y_P + u];
                float yv5 = Ysh[(o0 + 5)*Y_P + u];
#pragma unroll
                for (int j = 0; j < 5; j++) {
                    float mv = Msh[(u0 + j)*M_P + u];
                    h2a[0][j] = fmaf(yv0, mv, h2a[0][j]);
                    h2a[1][j] = fmaf(yv1, mv, h2a[1][j]);
                    h2a[2][j] = fmaf(yv2, mv, h2a[2][j]);
                    h2a[3][j] = fmaf(yv3, mv, h2a[3][j]);
                    h2a[4][j] = fmaf(yv4, mv, h2a[4][j]);
                    h2a[5][j] = fmaf(yv5, mv, h2a[5][j]);
                }
            }
        }
        __syncthreads();   // before next iteration overwrites Wsh/Msh/Ysh
    }

    // bias + relu, store z1, per-thread channel partial sums
    float* sredS = Ysh;                 // reuse (96*16)
    float* sredQ = Ysh + CC*16;         // (96*16) -- fits in 96*81
    if (act) {
#pragma unroll
        for (int i = 0; i < 6; i++) {
            int o = o0 + i;
            float b = bmlp[o];
            float s = 0.f, q = 0.f;
#pragma unroll
            for (int j = 0; j < 5; j++) {
                float r = h2a[i][j] + b;
                r = fmaxf(r, 0.f);
                g_z1[(blk*CC + o)*VLW + u0 + j] = r;
                s += r; q += r*r;
            }
            sredS[o*16 + ug] = s;
            sredQ[o*16 + ug] = q;
        }
    }
    __syncthreads();
    if (tid < CC) {
        float s = 0.f, q = 0.f;
        for (int g = 0; g < 15; g++) { s += sredS[tid*16 + g]; q += sredQ[tid*16 + g]; }
        g_p1[(blk*CC + tid)*2 + 0] = s;
        g_p1[(blk*CC + tid)*2 + 1] = q;
    }
}

// ---------------- stat reduction -> BN affine (a, c) ----------------
__global__ void k_stats(const float* __restrict__ part,
                        const float* __restrict__ gamma,
                        const float* __restrict__ beta,
                        float* __restrict__ sout, float inv_cnt) {
    __shared__ float rs[256], rq[256];
    const int o = blockIdx.x;
    float s = 0.f, q = 0.f;
    for (int b = threadIdx.x; b < NTB; b += 256) {
        s += part[(b*CC + o)*2 + 0];
        q += part[(b*CC + o)*2 + 1];
    }
    rs[threadIdx.x] = s; rq[threadIdx.x] = q;
    __syncthreads();
    for (int st = 128; st > 0; st >>= 1) {
        if (threadIdx.x < st) { rs[threadIdx.x] += rs[threadIdx.x + st];
                                rq[threadIdx.x] += rq[threadIdx.x + st]; }
        __syncthreads();
    }
    if (threadIdx.x == 0) {
        float mean = rs[0] * inv_cnt;
        float var  = rq[0] * inv_cnt - mean*mean;
        float a = gamma[o] * rsqrtf(var + EPS_F);
        sout[o*2 + 0] = a;
        sout[o*2 + 1] = beta[o] - mean*a;
    }
}

// ---------------- kernel 3: BN1+relu + window-collapse conv + stats ----------------
// smem: Hsh[96*76] | Wosh[96*289]
#define H_P  76
#define WO_P 289
#define SM3_FLOATS (CC*H_P + CC*WO_P)     // 35040 -> 140160 B

__global__ void k_outconv(const float* __restrict__ Wout,
                          const float* __restrict__ bout) {
    extern __shared__ float sm[];
    float* Hsh  = sm;
    float* Wosh = Hsh + CC*H_P;

    const int blk = blockIdx.x;
    const int tid = threadIdx.x;

    // BN1 + relu into shared
    for (int e = tid; e < CC*VLW; e += blockDim.x) {
        int o = e / VLW, u = e % VLW;
        float z = g_z1[(blk*CC + o)*VLW + u];
        float h = fmaxf(fmaf(g_s1[o*2], z, g_s1[o*2 + 1]), 0.f);
        Hsh[o*H_P + u] = h;
    }
    // W_out (o, i, w) -> Wosh[o][i*3+w]
    for (int e = tid; e < CC*CC*WINW; e += blockDim.x) {
        int o = e / (CC*WINW), k = e % (CC*WINW);
        Wosh[o*WO_P + k] = Wout[e];
    }
    __syncthreads();

    const bool act = (tid < 200);
    const int vv = tid % VV;
    const int og = tid / VV;     // 0..7
    const int o0 = og * 12;

    float acc[12];
#pragma unroll
    for (int r = 0; r < 12; r++) acc[r] = 0.f;

    if (act) {
        for (int i = 0; i < CC; i++) {
#pragma unroll
            for (int w = 0; w < WINW; w++) {
                float hv = Hsh[i*H_P + w*VV + vv];
                int k = i*WINW + w;
#pragma unroll
                for (int r = 0; r < 12; r++)
                    acc[r] = fmaf(Wosh[(o0 + r)*WO_P + k], hv, acc[r]);
            }
        }
    }
    __syncthreads();   // done reading Hsh; reuse for reduction

    float* sredS = Hsh;             // 96*25
    float* sredQ = Hsh + CC*VV;     // 96*25 (fits in 96*76)
    if (act) {
#pragma unroll
        for (int r = 0; r < 12; r++) {
            int o = o0 + r;
            float val = acc[r] + bout[o];
            g_outp[(blk*CC + o)*VV + vv] = val;
            sredS[o*VV + vv] = val;
            sredQ[o*VV + vv] = val*val;
        }
    }
    __syncthreads();
    if (tid < CC) {
        float s = 0.f, q = 0.f;
        for (int g = 0; g < VV; g++) { s += sredS[tid*VV + g]; q += sredQ[tid*VV + g]; }
        g_p2[(blk*CC + tid)*2 + 0] = s;
        g_p2[(blk*CC + tid)*2 + 1] = q;
    }
}

// ---------------- kernel 5: BN2 + layout transpose to (N,C,T,V) ----------------
__global__ void k_final(float* __restrict__ out) {
    int e = blockIdx.x * blockDim.x + threadIdx.x;
    if (e >= NB*CC*TT*VV) return;
    int vv = e % VV;
    int t  = (e / VV) % TT;
    int o  = (e / (VV*TT)) % CC;
    int n  = e / (VV*TT*CC);
    float v = g_outp[(((n*TT + t)*CC) + o)*VV + vv];
    out[e] = fmaf(g_s2[o*2], v, g_s2[o*2 + 1]);
}

// ---------------- launch ----------------
extern "C" void kernel_launch(void* const* d_in, const int* in_sizes, int n_in,
                              void* d_out, int out_size) {
    const float* x    = (const float*)d_in[0];
    const float* As   = (const float*)d_in[1];
    const float* Bs   = (const float*)d_in[2];
    const float* Ar   = (const float*)d_in[3];
    const float* Wmlp = (const float*)d_in[4];
    const float* bmlp = (const float*)d_in[5];
    const float* g1   = (const float*)d_in[6];
    const float* bt1  = (const float*)d_in[7];
    const float* Wout = (const float*)d_in[8];
    const float* bout = (const float*)d_in[9];
    const float* g2   = (const float*)d_in[10];
    const float* bt2  = (const float*)d_in[11];
    float* out = (float*)d_out;

    cudaFuncSetAttribute(k_aggmlp, cudaFuncAttributeMaxDynamicSharedMemorySize,
                         SM1_FLOATS * (int)sizeof(float));
    cudaFuncSetAttribute(k_outconv, cudaFuncAttributeMaxDynamicSharedMemorySize,
                         SM3_FLOATS * (int)sizeof(float));

    // __device__ symbols must be resolved to device addresses before being
    // passed as kernel arguments from host code.
    float *s1p = nullptr, *s2p = nullptr, *p1p = nullptr, *p2p = nullptr;
    cudaGetSymbolAddress((void**)&s1p, g_s1);
    cudaGetSymbolAddress((void**)&s2p, g_s2);
    cudaGetSymbolAddress((void**)&p1p, g_p1);
    cudaGetSymbolAddress((void**)&p2p, g_p2);

    k_eff<<<(NSC*VLW*VLW + 255)/256, 256>>>(As, Bs, Ar);
    k_aggmlp<<<NTB, 256, SM1_FLOATS * sizeof(float)>>>(x, Wmlp, bmlp);
    k_stats<<<CC, 256>>>(p1p, g1, bt1, s1p, 1.f / (float)(NB*TT*VLW));
    k_outconv<<<NTB, 256, SM3_FLOATS * sizeof(float)>>>(Wout, bout);
    k_stats<<<CC, 256>>>(p2p, g2, bt2, s2p, 1.f / (float)(NB*TT*VV));
    k_final<<<(NB*CC*TT*VV + 255)/256, 256>>>(out);
}

// round 3
// speedup vs baseline: 1.1431x; 1.1431x over previous
#include <cuda_runtime.h>
#include <string.h>

// MS-G3D fused forward, round 3: f32x2 packed FMA (FFMA2) in both GEMM stages,
// reduction-dim pairing (no packing instructions), swizzled W/Y smem, split
// k_outconv for 2 CTA/SM occupancy.
// Shapes: N=8, C=96, T=128, V=25, WIN=3, VL=75, NS=6.
#define NB    8
#define CC    96
#define TT    128
#define VV    25
#define WINW  3
#define VLW   75
#define NSC   6
#define NTB   (NB*TT)          // 1024 (n,t) tiles
#define DIN   (CC*NSC*2)       // 1152
#define EPS_F 1e-5f

// packed f32x2 fma: both lanes accumulate independent partial sums
#define F2(acc, a, b) asm("fma.rn.f32x2 %0, %1, %2, %0;" : "+l"(acc) : "l"(a), "l"(b))

static __device__ __forceinline__ float2 ull2f2(unsigned long long v) {
    float2 r; asm("mov.b64 {%0, %1}, %2;" : "=f"(r.x), "=f"(r.y) : "l"(v)); return r;
}

// ---------------- device scratch ----------------
__device__ float g_Aeff[NSC*VLW*VLW];
__device__ float g_Beff[NSC*VLW*VLW];
__device__ float g_z1[NTB*CC*VLW];           // 29.5 MB
__device__ float g_outp[NTB*CC*VV];          // 9.8 MB
__device__ float g_p1[NTB*CC*2];
__device__ float g_p2[NTB*CC*2];
__device__ float g_s1[CC*2];
__device__ float g_s2[CC*2];

// ---------------- kernel 0: effective adjacency ----------------
__global__ void k_eff(const float* __restrict__ As, const float* __restrict__ Bs,
                      const float* __restrict__ Ar) {
    int i = blockIdx.x * blockDim.x + threadIdx.x;
    if (i < NSC*VLW*VLW) {
        float r = Ar[i];
        g_Aeff[i] = As[i] + r;
        g_Beff[i] = Bs[i] + r;
    }
}

// ---------------- kernel 1: fused unfold + 12x (W @ Xu @ M^T) + bias + relu ----------------
// Thread tiling: og = tid%12 (o-strip of 8), ug = tid/12 (u/v'-strip of 4), 228 active.
// smem: XuT[76][100] (u,c) | Wsh[96][96] (o,c swizzled) | Msh[76][76] (v',u) | Ysh[96][96] (o,u swizzled)
#define XUT_P 100
#define W_P   96
#define M_P   76
#define Y_P   96
#define SM1_FLOATS (76*XUT_P + CC*W_P + 76*M_P + CC*Y_P)   // 31808 -> 127232 B

__global__ void __launch_bounds__(256, 1)
k_aggmlp(const float* __restrict__ x,
         const float* __restrict__ Wmlp,
         const float* __restrict__ bmlp) {
    extern __shared__ float sm[];
    float* XuT = sm;                       // 7600
    float* Wsh = XuT + 76*XUT_P;           // 9216
    float* Msh = Wsh + CC*W_P;             // 5776
    float* Ysh = Msh + 76*M_P;             // 9216

    const int blk = blockIdx.x;
    const int n = blk / TT;
    const int t = blk % TT;
    const int tid = threadIdx.x;

    // Build XuT[u][c] (transposed unfold), row u=75 zero, temporal zero pad.
    for (int e = tid; e < CC*76; e += 256) {
        int c = e / 76, u = e % 76;
        float val = 0.f;
        if (u < VLW) {
            int w = u / VV, v = u % VV;
            int tt = t + w - 1;
            if (tt >= 0 && tt < TT) val = x[((n*CC + c)*TT + tt)*VV + v];
        }
        XuT[u*XUT_P + c] = val;
    }

    const int og = tid % 12;
    const int ug = tid / 12;            // < 19 when act
    const int o0 = og * 8;
    const int u0 = ug * 4;              // u-strip (stage A) / v'-strip (stage B)
    const bool act = (tid < 228);
    const int swk = og & 7;

    unsigned long long h2p[8][4];
#pragma unroll
    for (int i = 0; i < 8; i++)
#pragma unroll
        for (int j = 0; j < 4; j++) h2p[i][j] = 0ull;

    for (int bs = 0; bs < 12; bs++) {
        const int branch = bs / NSC;
        const int s = bs % NSC;
        const int woff = branch * (NSC*CC) + s * CC;
        const float* Mg = (branch == 0 ? g_Aeff : g_Beff) + s*VLW*VLW;

        // W slice, columns XOR-swizzled by (o>>3)&7 in 16B granules
        for (int e = tid; e < CC*CC; e += 256) {
            int o = e / CC, c = e % CC;
            int col = (((c >> 2) ^ ((o >> 3) & 7)) << 2) | (c & 3);
            Wsh[o*W_P + col] = Wmlp[o*DIN + woff + c];
        }
        // M slice [v'][u], padded row/col 75 = 0
        for (int e = tid; e < 76*76; e += 256) {
            int vp = e / 76, u = e % 76;
            Msh[vp*M_P + u] = (vp < VLW && u < VLW) ? Mg[vp*VLW + u] : 0.f;
        }
        __syncthreads();

        if (act) {
            // Stage A: Y[o][u] = sum_c W[o][c] * XuT[u][c], paired over c.
            unsigned long long acc[8][4];
#pragma unroll
            for (int i = 0; i < 8; i++)
#pragma unroll
                for (int j = 0; j < 4; j++) acc[i][j] = 0ull;

            for (int cb = 0; cb < 24; cb++) {
                ulonglong2 xv[4];
#pragma unroll
                for (int j = 0; j < 4; j++)
                    xv[j] = *(const ulonglong2*)(XuT + (u0 + j)*XUT_P + cb*4);
                const int wc = ((cb ^ swk) << 2);
#pragma unroll
                for (int i = 0; i < 8; i++) {
                    ulonglong2 wv = *(const ulonglong2*)(Wsh + (o0 + i)*W_P + wc);
#pragma unroll
                    for (int j = 0; j < 4; j++) {
                        F2(acc[i][j], wv.x, xv[j].x);
                        F2(acc[i][j], wv.y, xv[j].y);
                    }
                }
            }
            // lane-reduce and store Y (swizzled columns)
            const int yc = ((ug ^ swk) << 2);
#pragma unroll
            for (int i = 0; i < 8; i++) {
                float4 yv;
                float2 a0 = ull2f2(acc[i][0]); yv.x = a0.x + a0.y;
                float2 a1 = ull2f2(acc[i][1]); yv.y = a1.x + a1.y;
                float2 a2 = ull2f2(acc[i][2]); yv.z = a2.x + a2.y;
                float2 a3 = ull2f2(acc[i][3]); yv.w = a3.x + a3.y;
                *(float4*)(Ysh + (o0 + i)*Y_P + yc) = yv;
            }
        }
        __syncthreads();

        if (act) {
            // Stage B: h2[o][v'] += sum_u Y[o][u] * M[v'][u], paired over u.
            for (int ub = 0; ub < 19; ub++) {
                ulonglong2 mv[4];
#pragma unroll
                for (int j = 0; j < 4; j++)
                    mv[j] = *(const ulonglong2*)(Msh + (u0 + j)*M_P + ub*4);
                const int yc2 = ((ub ^ swk) << 2);
#pragma unroll
                for (int i = 0; i < 8; i++) {
                    ulonglong2 yv = *(const ulonglong2*)(Ysh + (o0 + i)*Y_P + yc2);
#pragma unroll
                    for (int j = 0; j < 4; j++) {
                        F2(h2p[i][j], yv.x, mv[j].x);
                        F2(h2p[i][j], yv.y, mv[j].y);
                    }
                }
            }
        }
        __syncthreads();   // before next bs overwrites Wsh/Msh/Ysh
    }

    // bias + relu, store z1, per-block channel partials (reuse Wsh as scratch)
    float* sredS = Wsh;                 // 96*19
    float* sredQ = Wsh + CC*19;
    if (act) {
#pragma unroll
        for (int i = 0; i < 8; i++) {
            int o = o0 + i;
            float b = bmlp[o];
            float s = 0.f, q = 0.f;
#pragma unroll
            for (int j = 0; j < 4; j++) {
                int v = u0 + j;
                float2 p = ull2f2(h2p[i][j]);
                float r = fmaxf(p.x + p.y + b, 0.f);
                if (v < VLW) {
                    g_z1[(blk*CC + o)*VLW + v] = r;
                    s += r; q += r*r;
                }
            }
            sredS[o*19 + ug] = s;
            sredQ[o*19 + ug] = q;
        }
    }
    __syncthreads();
    if (tid < CC) {
        float s = 0.f, q = 0.f;
        for (int g = 0; g < 19; g++) { s += sredS[tid*19 + g]; q += sredQ[tid*19 + g]; }
        g_p1[(blk*CC + tid)*2 + 0] = s;
        g_p1[(blk*CC + tid)*2 + 1] = q;
    }
}

// ---------------- stat reduction -> BN affine (a, c) ----------------
__global__ void k_stats(const float* __restrict__ part,
                        const float* __restrict__ gamma,
                        const float* __restrict__ beta,
                        float* __restrict__ sout, float inv_cnt) {
    __shared__ float rs[256], rq[256];
    const int o = blockIdx.x;
    float s = 0.f, q = 0.f;
    for (int b = threadIdx.x; b < NTB; b += 256) {
        s += part[(b*CC + o)*2 + 0];
        q += part[(b*CC + o)*2 + 1];
    }
    rs[threadIdx.x] = s; rq[threadIdx.x] = q;
    __syncthreads();
    for (int st = 128; st > 0; st >>= 1) {
        if (threadIdx.x < st) { rs[threadIdx.x] += rs[threadIdx.x + st];
                                rq[threadIdx.x] += rq[threadIdx.x + st]; }
        __syncthreads();
    }
    if (threadIdx.x == 0) {
        float mean = rs[0] * inv_cnt;
        float var  = rq[0] * inv_cnt - mean*mean;
        float a = gamma[o] * rsqrtf(var + EPS_F);
        sout[o*2 + 0] = a;
        sout[o*2 + 1] = beta[o] - mean*a;
    }
}

// ---------------- kernel 3: BN1+relu + window conv (o split in 2) + stats ----------------
// blockIdx.x = (n,t), blockIdx.y = o-half. smem: HT[75][100] (u, i) | Wosh[48][292] (o, w*96+i)
#define HT_P  100
#define WO_P  292
#define SM3_FLOATS (VLW*HT_P + 48*WO_P)   // 21516 -> 86064 B

__global__ void __launch_bounds__(256, 2)
k_outconv(const float* __restrict__ Wout,
          const float* __restrict__ bout) {
    extern __shared__ float sm[];
    float* HT   = sm;                  // 7500
    float* Wosh = HT + VLW*HT_P;       // 14016

    const int blk  = blockIdx.x;
    const int half = blockIdx.y;
    const int tid  = threadIdx.x;

    // BN1 + relu, transposed to HT[u][i]
    for (int e = tid; e < CC*VLW; e += 256) {
        int o = e / VLW, u = e % VLW;
        float z = g_z1[(blk*CC + o)*VLW + u];
        HT[u*HT_P + o] = fmaxf(fmaf(g_s1[o*2], z, g_s1[o*2 + 1]), 0.f);
    }
    // W_out half: (o, i, w) -> Wosh[o_loc][w*96 + i]
    for (int e = tid; e < 48*CC*WINW; e += 256) {
        int ol = e / (CC*WINW), k = e % (CC*WINW);
        int i = k / WINW, w = k % WINW;
        Wosh[ol*WO_P + w*CC + i] = Wout[(half*48 + ol)*CC*WINW + k];
    }
    __syncthreads();

    const bool act = (tid < 200);
    const int vv = tid % VV;
    const int og = tid / VV;           // 0..7
    const int o0l = og * 6;

    unsigned long long acc2[6];
#pragma unroll
    for (int r = 0; r < 6; r++) acc2[r] = 0ull;

    if (act) {
#pragma unroll
        for (int w = 0; w < WINW; w++) {
            const float* hrow = HT + (w*VV + vv)*HT_P;
            const float* wbase = Wosh + w*CC;
            for (int ib = 0; ib < 24; ib++) {
                ulonglong2 hv = *(const ulonglong2*)(hrow + ib*4);
#pragma unroll
                for (int r = 0; r < 6; r++) {
                    ulonglong2 wv = *(const ulonglong2*)(wbase + (o0l + r)*WO_P + ib*4);
                    F2(acc2[r], wv.x, hv.x);
                    F2(acc2[r], wv.y, hv.y);
                }
            }
        }
    }
    __syncthreads();   // done with HT; reuse for reduction

    float* sredS = HT;                 // 48*25
    float* sredQ = HT + 48*VV;
    if (act) {
#pragma unroll
        for (int r = 0; r < 6; r++) {
            int ol = o0l + r;
            int o = half*48 + ol;
            float2 p = ull2f2(acc2[r]);
            float val = p.x + p.y + bout[o];
            g_outp[(blk*CC + o)*VV + vv] = val;
            sredS[ol*VV + vv] = val;
            sredQ[ol*VV + vv] = val*val;
        }
    }
    __syncthreads();
    if (tid < 48) {
        float s = 0.f, q = 0.f;
        for (int g = 0; g < VV; g++) { s += sredS[tid*VV + g]; q += sredQ[tid*VV + g]; }
        g_p2[(blk*CC + half*48 + tid)*2 + 0] = s;
        g_p2[(blk*CC + half*48 + tid)*2 + 1] = q;
    }
}

// ---------------- kernel 5: BN2 + transpose to (N,C,T,V) ----------------
__global__ void k_final(float* __restrict__ out) {
    int e = blockIdx.x * blockDim.x + threadIdx.x;
    if (e >= NB*CC*TT*VV) return;
    int vv = e % VV;
    int t  = (e / VV) % TT;
    int o  = (e / (VV*TT)) % CC;
    int n  = e / (VV*TT*CC);
    float v = g_outp[(((n*TT + t)*CC) + o)*VV + vv];
    out[e] = fmaf(g_s2[o*2], v, g_s2[o*2 + 1]);
}

// ---------------- launch ----------------
extern "C" void kernel_launch(void* const* d_in, const int* in_sizes, int n_in,
                              void* d_out, int out_size) {
    const float* x    = (const float*)d_in[0];
    const float* As   = (const float*)d_in[1];
    const float* Bs   = (const float*)d_in[2];
    const float* Ar   = (const float*)d_in[3];
    const float* Wmlp = (const float*)d_in[4];
    const float* bmlp = (const float*)d_in[5];
    const float* g1   = (const float*)d_in[6];
    const float* bt1  = (const float*)d_in[7];
    const float* Wout = (const float*)d_in[8];
    const float* bout = (const float*)d_in[9];
    const float* g2   = (const float*)d_in[10];
    const float* bt2  = (const float*)d_in[11];
    float* out = (float*)d_out;

    cudaFuncSetAttribute(k_aggmlp, cudaFuncAttributeMaxDynamicSharedMemorySize,
                         SM1_FLOATS * (int)sizeof(float));
    cudaFuncSetAttribute(k_outconv, cudaFuncAttributeMaxDynamicSharedMemorySize,
                         SM3_FLOATS * (int)sizeof(float));

    float *s1p = nullptr, *s2p = nullptr, *p1p = nullptr, *p2p = nullptr;
    cudaGetSymbolAddress((void**)&s1p, g_s1);
    cudaGetSymbolAddress((void**)&s2p, g_s2);
    cudaGetSymbolAddress((void**)&p1p, g_p1);
    cudaGetSymbolAddress((void**)&p2p, g_p2);

    k_eff<<<(NSC*VLW*VLW + 255)/256, 256>>>(As, Bs, Ar);
    k_aggmlp<<<NTB, 256, SM1_FLOATS * sizeof(float)>>>(x, Wmlp, bmlp);
    k_stats<<<CC, 256>>>(p1p, g1, bt1, s1p, 1.f / (float)(NB*TT*VLW));
    k_outconv<<<dim3(NTB, 2), 256, SM3_FLOATS * sizeof(float)>>>(Wout, bout);
    k_stats<<<CC, 256>>>(p2p, g2, bt2, s2p, 1.f / (float)(NB*TT*VV));
    k_final<<<(NB*CC*TT*VV + 255)/256, 256>>>(out);
}